// round 2
// baseline (speedup 1.0000x reference)
#include <cuda_runtime.h>

// Problem constants
#define TT 64
#define NROWS 2048
#define DD 512
#define ND (NROWS * DD)   // 1,048,576 elements per [N, D] state

__device__ float g_state0[ND];  // states[0]: used as carry, excluded from out0

__device__ __forceinline__ float sig_decay(float x) {
    const float DECAY = 0.6065306597126334f;  // exp(-0.5)
    return DECAY / (1.0f + __expf(-x));
}

// ---------------------------------------------------------------------------
// One recurrence step:
//   mm    = h_prev @ W[0:512,:] + static_t @ W[512:1024,:]
//   h_out = sigmoid(mm * thr + h_prev * (1 - thr)) * exp(-1/2)
// fp32 register-blocked GEMM: BM=128, BN=64, BK=16, 256 thr, 8x4 micro-tile.
// ---------------------------------------------------------------------------
#define BM 128
#define BN 64
#define BK 16
#define TM 8
#define TN 4

__global__ void __launch_bounds__(256, 1) step_kernel(
    const float* __restrict__ h_prev,  // [NROWS, DD]
    const float* __restrict__ stat,    // [NROWS, DD]
    const float* __restrict__ thr,     // [NROWS]
    const float* __restrict__ W,       // [2*DD, DD] row-major
    float* __restrict__ h_out)         // [NROWS, DD]
{
    __shared__ float As[BK][BM + 4];   // transposed A tile; row = 132 floats (528B, 16B-aligned)
    __shared__ float Bs[BK][BN];

    const int tid  = threadIdx.x;
    const int tx   = tid & 15;   // 0..15 (col group)
    const int ty   = tid >> 4;   // 0..15 (row group)
    const int row0 = blockIdx.y * BM;
    const int col0 = blockIdx.x * BN;

    // A-tile load map: 128x16 floats = 2 float4 per thread
    const int arow = tid >> 2;         // 0..63
    const int acol = (tid & 3) << 2;   // 0,4,8,12
    // B-tile load map: 16x64 floats = 1 float4 per thread
    const int brow = tid >> 4;         // 0..15
    const int bcol = (tid & 15) << 2;  // 0..60

    float acc[TM][TN];
#pragma unroll
    for (int m = 0; m < TM; ++m)
#pragma unroll
        for (int n = 0; n < TN; ++n) acc[m][n] = 0.0f;

#pragma unroll 1
    for (int phase = 0; phase < 2; ++phase) {
        const float* A  = phase ? stat : h_prev;
        const float* Wp = W + phase * DD * DD;  // rows [0:512) then [512:1024)

#pragma unroll 1
        for (int k0 = 0; k0 < DD; k0 += BK) {
            float4 a0 = *(const float4*)(A + (long long)(row0 + arow) * DD + k0 + acol);
            float4 a1 = *(const float4*)(A + (long long)(row0 + arow + 64) * DD + k0 + acol);
            float4 b0 = *(const float4*)(Wp + (long long)(k0 + brow) * DD + col0 + bcol);

            As[acol + 0][arow]      = a0.x;
            As[acol + 1][arow]      = a0.y;
            As[acol + 2][arow]      = a0.z;
            As[acol + 3][arow]      = a0.w;
            As[acol + 0][arow + 64] = a1.x;
            As[acol + 1][arow + 64] = a1.y;
            As[acol + 2][arow + 64] = a1.z;
            As[acol + 3][arow + 64] = a1.w;
            *(float4*)(&Bs[brow][bcol]) = b0;
            __syncthreads();

#pragma unroll
            for (int kk = 0; kk < BK; ++kk) {
                float4 ap = *(const float4*)(&As[kk][ty * TM]);
                float4 aq = *(const float4*)(&As[kk][ty * TM + 4]);
                float4 bv = *(const float4*)(&Bs[kk][tx * TN]);
                float av[TM] = {ap.x, ap.y, ap.z, ap.w, aq.x, aq.y, aq.z, aq.w};
                float bb[TN] = {bv.x, bv.y, bv.z, bv.w};
#pragma unroll
                for (int m = 0; m < TM; ++m)
#pragma unroll
                    for (int n = 0; n < TN; ++n)
                        acc[m][n] = fmaf(av[m], bb[n], acc[m][n]);
            }
            __syncthreads();
        }
    }

    // Epilogue: gated sigmoid update
#pragma unroll
    for (int m = 0; m < TM; ++m) {
        const int i   = row0 + ty * TM + m;
        const float t = thr[i];
        const float o = 1.0f - t;
        const long long base = (long long)i * DD + col0 + tx * TN;
        const float4 hp = *(const float4*)(h_prev + base);
        float4 r;
        r.x = sig_decay(acc[m][0] * t + hp.x * o);
        r.y = sig_decay(acc[m][1] * t + hp.y * o);
        r.z = sig_decay(acc[m][2] * t + hp.z * o);
        r.w = sig_decay(acc[m][3] * t + hp.w * o);
        *(float4*)(h_out + base) = r;
    }
}

// ---------------------------------------------------------------------------
// out2[t] = states[t+1] - states[t], t = 0..62
// states[0] lives in g_state0; states[t>=1] live in out0[t].
// ---------------------------------------------------------------------------
__global__ void diff_kernel(const float* __restrict__ s0,
                            const float* __restrict__ out0,
                            float* __restrict__ out2)
{
    long long idx = ((long long)blockIdx.x * blockDim.x + threadIdx.x) * 4;
    const long long total = 63LL * ND;
    if (idx >= total) return;
    const int t = (int)(idx / ND);
    const long long r = idx - (long long)t * ND;
    const float* sp1 = out0 + (long long)(t + 1) * ND + r;
    const float* sp0 = (t == 0) ? (s0 + r) : (out0 + (long long)t * ND + r);
    float4 a = *(const float4*)sp1;
    float4 b = *(const float4*)sp0;
    float4 d;
    d.x = a.x - b.x; d.y = a.y - b.y; d.z = a.z - b.z; d.w = a.w - b.w;
    *(float4*)(out2 + idx) = d;
}

// ---------------------------------------------------------------------------
// Inputs (metadata order):
//   d_in[0] all_data_static      [64, 2048, 512] f32
//   d_in[1] threshold_nc         [64, 2048, 1]   f32
//   d_in[2] all_data_dynamic_now [2048, 512]     f32
//   d_in[3] w1                   [1024, 512]     f32
// Output (concatenated, f32):
//   out0 [64, 2048, 512] = [h0, states[1..63]]
//   out1 [2048, 512]     = states[63]
//   out2 [63, 2048, 512] = states[1:] - states[:-1]
// ---------------------------------------------------------------------------
extern "C" void kernel_launch(void* const* d_in, const int* in_sizes, int n_in,
                              void* d_out, int out_size)
{
    const float* S   = (const float*)d_in[0];
    const float* thr = (const float*)d_in[1];
    const float* h0  = (const float*)d_in[2];
    const float* W   = (const float*)d_in[3];

    float* out0 = (float*)d_out;
    float* out1 = out0 + (long long)TT * ND;
    float* out2 = out1 + ND;

    float* s0 = nullptr;
    cudaGetSymbolAddress((void**)&s0, g_state0);

    const dim3 grid(DD / BN, NROWS / BM);  // (8, 16) = 128 blocks

    // Step 0: carry-only state -> scratch
    step_kernel<<<grid, 256>>>(h0, S, thr, W, s0);
    // out0[0] = h0 (faithful-to-source quirk)
    cudaMemcpyAsync(out0, h0, (size_t)ND * sizeof(float), cudaMemcpyDeviceToDevice);

    // Steps 1..63: write states[t] directly into out0[t]
    for (int t = 1; t < TT; ++t) {
        const float* hp = (t == 1) ? (const float*)s0 : (out0 + (long long)(t - 1) * ND);
        step_kernel<<<grid, 256>>>(hp,
                                   S + (long long)t * ND,
                                   thr + (long long)t * NROWS,
                                   W,
                                   out0 + (long long)t * ND);
    }

    // Final state
    cudaMemcpyAsync(out1, out0 + 63LL * ND, (size_t)ND * sizeof(float),
                    cudaMemcpyDeviceToDevice);

    // Diffs
    const long long total4 = (63LL * ND) / 4;
    const int threads = 256;
    const unsigned blocks = (unsigned)((total4 + threads - 1) / threads);
    diff_kernel<<<blocks, threads>>>(s0, out0, out2);
}

// round 7
// speedup vs baseline: 1.7191x; 1.7191x over previous
#include <cuda_runtime.h>
#include <cuda_bf16.h>
#include <cstdint>

// Problem constants
#define TT 64
#define NROWS 2048
#define DD 512
#define KDIM (2*DD)            // 1024
#define ND (NROWS * DD)        // 1,048,576

// ---------------------------------------------------------------------------
// Device scratch (no allocations allowed)
// ---------------------------------------------------------------------------
__device__ float g_state0[ND];                       // states[0] fp32 (carry only)
__device__ __nv_bfloat16 g_h_hi[2][ND];              // ping-pong bf16 split of h
__device__ __nv_bfloat16 g_h_lo[2][ND];
__device__ __nv_bfloat16 g_wt_hi[DD * KDIM];         // W^T split: [512 n][1024 k]
__device__ __nv_bfloat16 g_wt_lo[DD * KDIM];

// ---------------------------------------------------------------------------
// Warp-level tensor core primitives (sm_80+ PTX, safe for compute_103)
// ---------------------------------------------------------------------------
__device__ __forceinline__ uint32_t smem_u32(const void* p) {
    uint32_t a;
    asm("{ .reg .u64 t; cvta.to.shared.u64 t, %1; cvt.u32.u64 %0, t; }"
        : "=r"(a) : "l"(p));
    return a;
}

__device__ __forceinline__ void ldsm_x4(uint32_t* r, uint32_t addr) {
    asm volatile("ldmatrix.sync.aligned.m8n8.x4.shared.b16 {%0,%1,%2,%3}, [%4];"
                 : "=r"(r[0]), "=r"(r[1]), "=r"(r[2]), "=r"(r[3]) : "r"(addr));
}
__device__ __forceinline__ void ldsm_x2(uint32_t* r, uint32_t addr) {
    asm volatile("ldmatrix.sync.aligned.m8n8.x2.shared.b16 {%0,%1}, [%2];"
                 : "=r"(r[0]), "=r"(r[1]) : "r"(addr));
}

__device__ __forceinline__ void mma_bf16(float* d, const uint32_t* a,
                                         const uint32_t* b) {
    asm volatile(
        "mma.sync.aligned.m16n8k16.row.col.f32.bf16.bf16.f32 "
        "{%0,%1,%2,%3}, {%4,%5,%6,%7}, {%8,%9}, {%0,%1,%2,%3};"
        : "+f"(d[0]), "+f"(d[1]), "+f"(d[2]), "+f"(d[3])
        : "r"(a[0]), "r"(a[1]), "r"(a[2]), "r"(a[3]), "r"(b[0]), "r"(b[1]));
}

union U8b { __nv_bfloat16 h[8]; uint4 v; };

// ---------------------------------------------------------------------------
// Step kernel:
//   MM = h_prev @ W[0:512] + static_t @ W[512:1024]   (split-bf16, fp32 acc)
//   h  = sigmoid(MM*thr + h_prev*(1-thr)) * exp(-1/2)
// CTA tile 128x64, 8 warps (4M x 2N), warp tile 32x32, BK=32.
// ---------------------------------------------------------------------------
#define BM 128
#define BN 64
#define BK 32
#define NCHUNK (KDIM / BK)     // 32
#define AS_STRIDE 40           // bf16 units per smem row (32 data + 8 pad = 80B)
#define BS_STRIDE 40

__global__ void __launch_bounds__(256, 1) step_mma_kernel(
    const __nv_bfloat16* __restrict__ h_hi,   // [N, DD] bf16 hi of h_prev
    const __nv_bfloat16* __restrict__ h_lo,   // [N, DD] bf16 lo of h_prev
    const float* __restrict__ h_prev,         // [N, DD] fp32 h_prev (gate input)
    const float* __restrict__ stat,           // [N, DD] static_t fp32
    const float* __restrict__ thr,            // [N]
    const __nv_bfloat16* __restrict__ wt_hi,  // [DD, KDIM] W^T hi
    const __nv_bfloat16* __restrict__ wt_lo,  // [DD, KDIM] W^T lo
    float* __restrict__ h_out,                // [N, DD] fp32
    __nv_bfloat16* __restrict__ o_hi,         // split of new h
    __nv_bfloat16* __restrict__ o_lo)
{
    __shared__ __nv_bfloat16 As_hi[BM][AS_STRIDE];
    __shared__ __nv_bfloat16 As_lo[BM][AS_STRIDE];
    __shared__ __nv_bfloat16 Bs_hi[BN][BS_STRIDE];
    __shared__ __nv_bfloat16 Bs_lo[BN][BS_STRIDE];

    const int tid  = threadIdx.x;
    const int lane = tid & 31;
    const int warp = tid >> 5;
    const int wm   = warp >> 1;          // 0..3
    const int wn   = warp & 1;           // 0..1
    const int m_base = wm * 32;
    const int n_base = wn * 32;
    const int row0 = blockIdx.y * BM;
    const int col0 = blockIdx.x * BN;

    // staging maps
    const int arow = tid >> 2;           // 0..63 (rows arow, arow+64)
    const int aq   = tid & 3;            // uint4 index in row
    const int brow = tid >> 2;
    const int bq   = tid & 3;

    // ldmatrix lane maps
    const int a_lrow = (lane & 7) + ((lane >> 3) & 1) * 8;  // row within 16
    const int a_koff = ((lane >> 4) & 1) * 8;               // 0 or 8
    const int b_lrow = lane & 7;
    const int b_koff = ((lane >> 3) & 1) * 8;

    const uint32_t sa_hi = smem_u32(As_hi);
    const uint32_t sa_lo = smem_u32(As_lo);
    const uint32_t sb_hi = smem_u32(Bs_hi);
    const uint32_t sb_lo = smem_u32(Bs_lo);

    float acc[2][4][4];
#pragma unroll
    for (int mi = 0; mi < 2; ++mi)
#pragma unroll
        for (int ni = 0; ni < 4; ++ni)
#pragma unroll
            for (int j = 0; j < 4; ++j) acc[mi][ni][j] = 0.0f;

    uint4 pa_hi[2], pa_lo[2], pb_hi, pb_lo;

#define LOAD_CHUNK(c) do {                                                    \
    const int _ph  = (c) >> 4;                                                \
    const int _kkA = ((c) & 15) * BK;                                         \
    const int _kkW = (c) * BK;                                                \
    if (_ph == 0) {                                                           \
        _Pragma("unroll")                                                     \
        for (int i = 0; i < 2; ++i) {                                         \
            const size_t off = (size_t)(row0 + arow + i * 64) * DD + _kkA + aq * 8; \
            pa_hi[i] = *(const uint4*)(h_hi + off);                           \
            pa_lo[i] = *(const uint4*)(h_lo + off);                           \
        }                                                                     \
    } else {                                                                  \
        _Pragma("unroll")                                                     \
        for (int i = 0; i < 2; ++i) {                                         \
            const float* s = stat + (size_t)(row0 + arow + i * 64) * DD + _kkA + aq * 8; \
            const float4 f0 = *(const float4*)s;                              \
            const float4 f1 = *(const float4*)(s + 4);                        \
            const float v[8] = {f0.x, f0.y, f0.z, f0.w, f1.x, f1.y, f1.z, f1.w}; \
            U8b hb, lb;                                                       \
            _Pragma("unroll")                                                 \
            for (int j = 0; j < 8; ++j) {                                     \
                hb.h[j] = __float2bfloat16(v[j]);                             \
                lb.h[j] = __float2bfloat16(v[j] - __bfloat162float(hb.h[j])); \
            }                                                                 \
            pa_hi[i] = hb.v; pa_lo[i] = lb.v;                                 \
        }                                                                     \
    }                                                                         \
    {                                                                         \
        const size_t off = (size_t)(col0 + brow) * KDIM + _kkW + bq * 8;      \
        pb_hi = *(const uint4*)(wt_hi + off);                                 \
        pb_lo = *(const uint4*)(wt_lo + off);                                 \
    }                                                                         \
} while (0)

    LOAD_CHUNK(0);

#pragma unroll 1
    for (int c = 0; c < NCHUNK; ++c) {
        // store prefetched regs -> smem
#pragma unroll
        for (int i = 0; i < 2; ++i) {
            *(uint4*)&As_hi[arow + i * 64][aq * 8] = pa_hi[i];
            *(uint4*)&As_lo[arow + i * 64][aq * 8] = pa_lo[i];
        }
        *(uint4*)&Bs_hi[brow][bq * 8] = pb_hi;
        *(uint4*)&Bs_lo[brow][bq * 8] = pb_lo;
        __syncthreads();

        if (c + 1 < NCHUNK) LOAD_CHUNK(c + 1);

        // compute: 2 k-steps of 16
#pragma unroll
        for (int ks = 0; ks < 2; ++ks) {
            const int k0 = ks * 16;
            uint32_t af_hi[2][4], af_lo[2][4], bf_hi[4][2], bf_lo[4][2];
#pragma unroll
            for (int mi = 0; mi < 2; ++mi) {
                const uint32_t ro =
                    (uint32_t)((m_base + mi * 16 + a_lrow) * AS_STRIDE +
                               k0 + a_koff) * 2;
                ldsm_x4(af_hi[mi], sa_hi + ro);
                ldsm_x4(af_lo[mi], sa_lo + ro);
            }
#pragma unroll
            for (int ni = 0; ni < 4; ++ni) {
                const uint32_t ro =
                    (uint32_t)((n_base + ni * 8 + b_lrow) * BS_STRIDE +
                               k0 + b_koff) * 2;
                ldsm_x2(bf_hi[ni], sb_hi + ro);
                ldsm_x2(bf_lo[ni], sb_lo + ro);
            }
#pragma unroll
            for (int mi = 0; mi < 2; ++mi)
#pragma unroll
                for (int ni = 0; ni < 4; ++ni) {
                    mma_bf16(acc[mi][ni], af_hi[mi], bf_hi[ni]);  // hi*hi
                    mma_bf16(acc[mi][ni], af_hi[mi], bf_lo[ni]);  // hi*lo
                    mma_bf16(acc[mi][ni], af_lo[mi], bf_hi[ni]);  // lo*hi
                }
        }
        __syncthreads();
    }

    // ---- epilogue: gated sigmoid update, write fp32 state + bf16 split ----
    const float DEC = 0.6065306597126334f;  // exp(-0.5)
    const int tr = lane >> 2;
    const int tg = lane & 3;
#pragma unroll
    for (int mi = 0; mi < 2; ++mi) {
#pragma unroll
        for (int half = 0; half < 2; ++half) {
            const int r = row0 + m_base + mi * 16 + tr + half * 8;
            const float tv = thr[r];
            const float ov = 1.0f - tv;
            const size_t base = (size_t)r * DD;
#pragma unroll
            for (int ni = 0; ni < 4; ++ni) {
                const int cn = col0 + n_base + ni * 8 + 2 * tg;
                const float2 hp = *(const float2*)(h_prev + base + cn);
                const float z0 = acc[mi][ni][half * 2 + 0] * tv + hp.x * ov;
                const float z1 = acc[mi][ni][half * 2 + 1] * tv + hp.y * ov;
                float2 res;
                res.x = DEC / (1.0f + __expf(-z0));
                res.y = DEC / (1.0f + __expf(-z1));
                *(float2*)(h_out + base + cn) = res;

                __nv_bfloat162 hh, ll;
                hh.x = __float2bfloat16(res.x);
                hh.y = __float2bfloat16(res.y);
                ll.x = __float2bfloat16(res.x - __bfloat162float(hh.x));
                ll.y = __float2bfloat16(res.y - __bfloat162float(hh.y));
                *(__nv_bfloat162*)(o_hi + base + cn) = hh;
                *(__nv_bfloat162*)(o_lo + base + cn) = ll;
            }
        }
    }
}

// ---------------------------------------------------------------------------
// Prep: transpose + split W  ->  Wt[n][k] = W[k][n], bf16 hi/lo
// ---------------------------------------------------------------------------
__global__ void prep_w_kernel(const float* __restrict__ W,
                              __nv_bfloat16* __restrict__ wt_hi,
                              __nv_bfloat16* __restrict__ wt_lo)
{
    __shared__ float tile[32][33];
    const int n0 = blockIdx.x * 32;
    const int k0 = blockIdx.y * 32;
    const int tx = threadIdx.x;       // 0..31
    const int ty = threadIdx.y;       // 0..7
#pragma unroll
    for (int i = 0; i < 4; ++i)
        tile[ty + i * 8][tx] = W[(size_t)(k0 + ty + i * 8) * DD + n0 + tx];
    __syncthreads();
#pragma unroll
    for (int i = 0; i < 4; ++i) {
        const int a = ty + i * 8;
        const float v = tile[tx][a];
        const __nv_bfloat16 hb = __float2bfloat16(v);
        const size_t dst = (size_t)(n0 + a) * KDIM + k0 + tx;
        wt_hi[dst] = hb;
        wt_lo[dst] = __float2bfloat16(v - __bfloat162float(hb));
    }
}

// ---------------------------------------------------------------------------
// Prep: split h0 fp32 -> bf16 hi/lo
// ---------------------------------------------------------------------------
__global__ void split_kernel(const float* __restrict__ x,
                             __nv_bfloat16* __restrict__ hi,
                             __nv_bfloat16* __restrict__ lo)
{
    const size_t i = ((size_t)blockIdx.x * blockDim.x + threadIdx.x) * 4;
    if (i >= ND) return;
    const float4 v = *(const float4*)(x + i);
    __nv_bfloat162 h01, h23, l01, l23;
    h01.x = __float2bfloat16(v.x); h01.y = __float2bfloat16(v.y);
    h23.x = __float2bfloat16(v.z); h23.y = __float2bfloat16(v.w);
    l01.x = __float2bfloat16(v.x - __bfloat162float(h01.x));
    l01.y = __float2bfloat16(v.y - __bfloat162float(h01.y));
    l23.x = __float2bfloat16(v.z - __bfloat162float(h23.x));
    l23.y = __float2bfloat16(v.w - __bfloat162float(h23.y));
    *(__nv_bfloat162*)(hi + i)     = h01;
    *(__nv_bfloat162*)(hi + i + 2) = h23;
    *(__nv_bfloat162*)(lo + i)     = l01;
    *(__nv_bfloat162*)(lo + i + 2) = l23;
}

// ---------------------------------------------------------------------------
// out2[t] = states[t+1] - states[t]
// ---------------------------------------------------------------------------
__global__ void diff_kernel(const float* __restrict__ s0,
                            const float* __restrict__ out0,
                            float* __restrict__ out2)
{
    long long idx = ((long long)blockIdx.x * blockDim.x + threadIdx.x) * 4;
    const long long total = 63LL * ND;
    if (idx >= total) return;
    const int t = (int)(idx / ND);
    const long long r = idx - (long long)t * ND;
    const float* sp1 = out0 + (long long)(t + 1) * ND + r;
    const float* sp0 = (t == 0) ? (s0 + r) : (out0 + (long long)t * ND + r);
    float4 a = *(const float4*)sp1;
    float4 b = *(const float4*)sp0;
    float4 d;
    d.x = a.x - b.x; d.y = a.y - b.y; d.z = a.z - b.z; d.w = a.w - b.w;
    *(float4*)(out2 + idx) = d;
}

// ---------------------------------------------------------------------------
// Inputs: static [64,2048,512], thr [64,2048,1], h0 [2048,512], w1 [1024,512]
// Output: out0 [64,2048,512] | out1 [2048,512] | out2 [63,2048,512]
// ---------------------------------------------------------------------------
extern "C" void kernel_launch(void* const* d_in, const int* in_sizes, int n_in,
                              void* d_out, int out_size)
{
    const float* S   = (const float*)d_in[0];
    const float* thr = (const float*)d_in[1];
    const float* h0  = (const float*)d_in[2];
    const float* W   = (const float*)d_in[3];

    float* out0 = (float*)d_out;
    float* out1 = out0 + (long long)TT * ND;
    float* out2 = out1 + ND;

    float* s0 = nullptr;
    __nv_bfloat16 *hhi = nullptr, *hlo = nullptr, *wth = nullptr, *wtl = nullptr;
    cudaGetSymbolAddress((void**)&s0, g_state0);
    cudaGetSymbolAddress((void**)&hhi, g_h_hi);
    cudaGetSymbolAddress((void**)&hlo, g_h_lo);
    cudaGetSymbolAddress((void**)&wth, g_wt_hi);
    cudaGetSymbolAddress((void**)&wtl, g_wt_lo);
    __nv_bfloat16* hhi_b[2] = {hhi, hhi + ND};
    __nv_bfloat16* hlo_b[2] = {hlo, hlo + ND};

    // one-time prep (per launch; cheap)
    prep_w_kernel<<<dim3(16, 32), dim3(32, 8)>>>(W, wth, wtl);
    split_kernel<<<ND / 4 / 256, 256>>>(h0, hhi_b[0], hlo_b[0]);

    const dim3 grid(DD / BN, NROWS / BM);  // (8, 16) = 128 CTAs

    // t = 0: carry-only state -> scratch; reads split buf0, writes buf1
    step_mma_kernel<<<grid, 256>>>(
        hhi_b[0], hlo_b[0], h0, S, thr, wth, wtl, s0, hhi_b[1], hlo_b[1]);
    cudaMemcpyAsync(out0, h0, (size_t)ND * sizeof(float), cudaMemcpyDeviceToDevice);

    for (int t = 1; t < TT; ++t) {
        const int in = t & 1;
        const float* hp = (t == 1) ? (const float*)s0
                                   : (out0 + (long long)(t - 1) * ND);
        step_mma_kernel<<<grid, 256>>>(
            hhi_b[in], hlo_b[in], hp,
            S + (long long)t * ND, thr + (long long)t * NROWS,
            wth, wtl,
            out0 + (long long)t * ND,
            hhi_b[in ^ 1], hlo_b[in ^ 1]);
    }

    cudaMemcpyAsync(out1, out0 + 63LL * ND, (size_t)ND * sizeof(float),
                    cudaMemcpyDeviceToDevice);

    const long long total4 = (63LL * ND) / 4;
    const int threads = 256;
    const unsigned blocks = (unsigned)((total4 + threads - 1) / threads);
    diff_kernel<<<blocks, threads>>>(s0, out0, out2);
}

// round 8
// speedup vs baseline: 2.1410x; 1.2454x over previous
#include <cuda_runtime.h>
#include <cuda_bf16.h>
#include <cstdint>

// Problem constants
#define TT 64
#define NROWS 2048
#define DD 512
#define KDIM (2*DD)            // 1024
#define ND (NROWS * DD)        // 1,048,576

// ---------------------------------------------------------------------------
// Device scratch (no allocations allowed)
// ---------------------------------------------------------------------------
__device__ float g_state0[ND];                       // states[0] fp32 (carry only)
__device__ __nv_bfloat16 g_h_hi[2][ND];              // ping-pong bf16 split of h
__device__ __nv_bfloat16 g_h_lo[2][ND];
__device__ __nv_bfloat16 g_wt_hi[DD * KDIM];         // W^T split: [512 n][1024 k]
__device__ __nv_bfloat16 g_wt_lo[DD * KDIM];
__device__ __nv_bfloat16 g_s_hi[TT * ND];            // pre-split static (hi)
__device__ __nv_bfloat16 g_s_lo[TT * ND];            // pre-split static (lo)

// ---------------------------------------------------------------------------
// Warp-level primitives (sm_80+ PTX, safe for compute_103)
// ---------------------------------------------------------------------------
__device__ __forceinline__ uint32_t smem_u32(const void* p) {
    uint32_t a;
    asm("{ .reg .u64 t; cvta.to.shared.u64 t, %1; cvt.u32.u64 %0, t; }"
        : "=r"(a) : "l"(p));
    return a;
}

__device__ __forceinline__ void ldsm_x4(uint32_t* r, uint32_t addr) {
    asm volatile("ldmatrix.sync.aligned.m8n8.x4.shared.b16 {%0,%1,%2,%3}, [%4];"
                 : "=r"(r[0]), "=r"(r[1]), "=r"(r[2]), "=r"(r[3]) : "r"(addr));
}
__device__ __forceinline__ void ldsm_x2(uint32_t* r, uint32_t addr) {
    asm volatile("ldmatrix.sync.aligned.m8n8.x2.shared.b16 {%0,%1}, [%2];"
                 : "=r"(r[0]), "=r"(r[1]) : "r"(addr));
}

__device__ __forceinline__ void mma_bf16(float* d, const uint32_t* a,
                                         const uint32_t* b) {
    asm volatile(
        "mma.sync.aligned.m16n8k16.row.col.f32.bf16.bf16.f32 "
        "{%0,%1,%2,%3}, {%4,%5,%6,%7}, {%8,%9}, {%0,%1,%2,%3};"
        : "+f"(d[0]), "+f"(d[1]), "+f"(d[2]), "+f"(d[3])
        : "r"(a[0]), "r"(a[1]), "r"(a[2]), "r"(a[3]), "r"(b[0]), "r"(b[1]));
}

__device__ __forceinline__ void cp16(uint32_t dst, const void* src) {
    asm volatile("cp.async.cg.shared.global [%0], [%1], 16;"
                 :: "r"(dst), "l"(src));
}
__device__ __forceinline__ void cp_commit() {
    asm volatile("cp.async.commit_group;");
}
template <int N>
__device__ __forceinline__ void cp_wait() {
    asm volatile("cp.async.wait_group %0;" :: "n"(N));
}

// ---------------------------------------------------------------------------
// Step kernel:
//   MM = h_prev @ W[0:512] + static_t @ W[512:1024]   (split-bf16, fp32 acc)
//   h  = sigmoid(MM*thr + h_prev*(1-thr)) * exp(-1/2)
// CTA tile 128x64, 8 warps (4M x 2N), warp tile 32x32, BK=32.
// 4-stage cp.async smem pipeline.
// ---------------------------------------------------------------------------
#define BM 128
#define BN 64
#define BK 32
#define NCHUNK (KDIM / BK)     // 32
#define STAGES 4
#define AS_STRIDE 40           // bf16 units per smem row (32 data + 8 pad = 80B)

// per-stage byte offsets within a stage (each tile row = 80B)
#define ST_AHI 0
#define ST_ALO 10240           // 128*80
#define ST_BHI 20480
#define ST_BLO 25600           // + 64*80
#define STAGE_BYTES 30720
#define SMEM_TOTAL (STAGES * STAGE_BYTES)   // 122880

__global__ void __launch_bounds__(256, 1) step_mma_kernel(
    const __nv_bfloat16* __restrict__ h_hi,   // [N, DD] phase-0 A (hi)
    const __nv_bfloat16* __restrict__ h_lo,
    const __nv_bfloat16* __restrict__ s_hi,   // [N, DD] phase-1 A (hi), this step
    const __nv_bfloat16* __restrict__ s_lo,
    const float* __restrict__ h_prev,         // [N, DD] fp32 (gate input)
    const float* __restrict__ thr,            // [N]
    const __nv_bfloat16* __restrict__ wt_hi,  // [DD, KDIM] W^T hi
    const __nv_bfloat16* __restrict__ wt_lo,
    float* __restrict__ h_out,                // [N, DD] fp32
    __nv_bfloat16* __restrict__ o_hi,         // split of new h
    __nv_bfloat16* __restrict__ o_lo)
{
    extern __shared__ char smem[];
    const uint32_t sb = smem_u32(smem);

    const int tid  = threadIdx.x;
    const int lane = tid & 31;
    const int warp = tid >> 5;
    const int wm   = warp >> 1;          // 0..3
    const int wn   = warp & 1;           // 0..1
    const int m_base = wm * 32;
    const int n_base = wn * 32;
    const int row0 = blockIdx.y * BM;
    const int col0 = blockIdx.x * BN;

    // ldmatrix lane maps
    const int a_lrow = (lane & 7) + ((lane >> 3) & 1) * 8;
    const int a_koff = ((lane >> 4) & 1) * 8;
    const int b_lrow = lane & 7;
    const int b_koff = ((lane >> 3) & 1) * 8;

    float acc[2][4][4];
#pragma unroll
    for (int mi = 0; mi < 2; ++mi)
#pragma unroll
        for (int ni = 0; ni < 4; ++ni)
#pragma unroll
            for (int j = 0; j < 4; ++j) acc[mi][ni][j] = 0.0f;

    // ---- async tile fill for chunk c into stage (c % STAGES) ----
    // A: 128 rows x 32 k (2 tiles hi/lo): 512 cp16 ops each -> 2/thread
    // B:  64 rows x 32 k: 256 cp16 ops each -> 1/thread
    auto issue_chunk = [&](int c) {
        const uint32_t st = sb + (uint32_t)(c & (STAGES - 1)) * STAGE_BYTES;
        const int ph  = c >> 4;
        const int kkA = (c & 15) * BK;
        const int kkW = c * BK;
        const __nv_bfloat16* ah = ph ? s_hi : h_hi;
        const __nv_bfloat16* al = ph ? s_lo : h_lo;
#pragma unroll
        for (int i = 0; i < 2; ++i) {
            const int o = tid + i * 256;       // 0..511
            const int r = o >> 2;
            const int q = o & 3;
            const size_t src = (size_t)(row0 + r) * DD + kkA + q * 8;
            const uint32_t dst = st + (uint32_t)(r * 80 + q * 16);
            cp16(dst + ST_AHI, ah + src);
            cp16(dst + ST_ALO, al + src);
        }
        {
            const int r = tid >> 2;
            const int q = tid & 3;
            const size_t src = (size_t)(col0 + r) * KDIM + kkW + q * 8;
            const uint32_t dst = st + (uint32_t)(r * 80 + q * 16);
            cp16(dst + ST_BHI, wt_hi + src);
            cp16(dst + ST_BLO, wt_lo + src);
        }
        cp_commit();
    };

    // prologue: stages 0..2 in flight
    issue_chunk(0);
    issue_chunk(1);
    issue_chunk(2);

#pragma unroll 1
    for (int c = 0; c < NCHUNK; ++c) {
        cp_wait<2>();            // chunk c landed
        __syncthreads();         // all warps done with stage (c+3)%4's old data

        if (c + 3 < NCHUNK) issue_chunk(c + 3);
        else cp_commit();        // keep group count consistent

        const uint32_t st = sb + (uint32_t)(c & (STAGES - 1)) * STAGE_BYTES;

#pragma unroll
        for (int ks = 0; ks < 2; ++ks) {
            const int k0 = ks * 16;
            uint32_t af_hi[2][4], af_lo[2][4], bf_hi[4][2], bf_lo[4][2];
#pragma unroll
            for (int mi = 0; mi < 2; ++mi) {
                const uint32_t ro =
                    (uint32_t)((m_base + mi * 16 + a_lrow) * 80 +
                               (k0 + a_koff) * 2);
                ldsm_x4(af_hi[mi], st + ST_AHI + ro);
                ldsm_x4(af_lo[mi], st + ST_ALO + ro);
            }
#pragma unroll
            for (int ni = 0; ni < 4; ++ni) {
                const uint32_t ro =
                    (uint32_t)((n_base + ni * 8 + b_lrow) * 80 +
                               (k0 + b_koff) * 2);
                ldsm_x2(bf_hi[ni], st + ST_BHI + ro);
                ldsm_x2(bf_lo[ni], st + ST_BLO + ro);
            }
#pragma unroll
            for (int mi = 0; mi < 2; ++mi)
#pragma unroll
                for (int ni = 0; ni < 4; ++ni) {
                    mma_bf16(acc[mi][ni], af_hi[mi], bf_hi[ni]);  // hi*hi
                    mma_bf16(acc[mi][ni], af_hi[mi], bf_lo[ni]);  // hi*lo
                    mma_bf16(acc[mi][ni], af_lo[mi], bf_hi[ni]);  // lo*hi
                }
        }
        __syncthreads();
    }

    // ---- epilogue: gated sigmoid update, write fp32 state + bf16 split ----
    const float DEC = 0.6065306597126334f;  // exp(-0.5)
    const int tr = lane >> 2;
    const int tg = lane & 3;
#pragma unroll
    for (int mi = 0; mi < 2; ++mi) {
#pragma unroll
        for (int half = 0; half < 2; ++half) {
            const int r = row0 + m_base + mi * 16 + tr + half * 8;
            const float tv = thr[r];
            const float ov = 1.0f - tv;
            const size_t base = (size_t)r * DD;
#pragma unroll
            for (int ni = 0; ni < 4; ++ni) {
                const int cn = col0 + n_base + ni * 8 + 2 * tg;
                const float2 hp = *(const float2*)(h_prev + base + cn);
                const float z0 = acc[mi][ni][half * 2 + 0] * tv + hp.x * ov;
                const float z1 = acc[mi][ni][half * 2 + 1] * tv + hp.y * ov;
                float2 res;
                res.x = DEC / (1.0f + __expf(-z0));
                res.y = DEC / (1.0f + __expf(-z1));
                *(float2*)(h_out + base + cn) = res;

                __nv_bfloat162 hh, ll;
                hh.x = __float2bfloat16(res.x);
                hh.y = __float2bfloat16(res.y);
                ll.x = __float2bfloat16(res.x - __bfloat162float(hh.x));
                ll.y = __float2bfloat16(res.y - __bfloat162float(hh.y));
                *(__nv_bfloat162*)(o_hi + base + cn) = hh;
                *(__nv_bfloat162*)(o_lo + base + cn) = ll;
            }
        }
    }
}

// ---------------------------------------------------------------------------
// Prep: transpose + split W  ->  Wt[n][k] = W[k][n], bf16 hi/lo
// ---------------------------------------------------------------------------
__global__ void prep_w_kernel(const float* __restrict__ W,
                              __nv_bfloat16* __restrict__ wt_hi,
                              __nv_bfloat16* __restrict__ wt_lo)
{
    __shared__ float tile[32][33];
    const int n0 = blockIdx.x * 32;
    const int k0 = blockIdx.y * 32;
    const int tx = threadIdx.x;       // 0..31
    const int ty = threadIdx.y;       // 0..7
#pragma unroll
    for (int i = 0; i < 4; ++i)
        tile[ty + i * 8][tx] = W[(size_t)(k0 + ty + i * 8) * DD + n0 + tx];
    __syncthreads();
#pragma unroll
    for (int i = 0; i < 4; ++i) {
        const int a = ty + i * 8;
        const float v = tile[tx][a];
        const __nv_bfloat16 hb = __float2bfloat16(v);
        const size_t dst = (size_t)(n0 + a) * KDIM + k0 + tx;
        wt_hi[dst] = hb;
        wt_lo[dst] = __float2bfloat16(v - __bfloat162float(hb));
    }
}

// ---------------------------------------------------------------------------
// Split fp32 -> bf16 hi/lo (used for h0 and for ALL static data)
// ---------------------------------------------------------------------------
__global__ void split_kernel(const float* __restrict__ x,
                             __nv_bfloat16* __restrict__ hi,
                             __nv_bfloat16* __restrict__ lo,
                             long long n_elem)
{
    const long long i = ((long long)blockIdx.x * blockDim.x + threadIdx.x) * 4;
    if (i >= n_elem) return;
    const float4 v = *(const float4*)(x + i);
    __nv_bfloat162 h01, h23, l01, l23;
    h01.x = __float2bfloat16(v.x); h01.y = __float2bfloat16(v.y);
    h23.x = __float2bfloat16(v.z); h23.y = __float2bfloat16(v.w);
    l01.x = __float2bfloat16(v.x - __bfloat162float(h01.x));
    l01.y = __float2bfloat16(v.y - __bfloat162float(h01.y));
    l23.x = __float2bfloat16(v.z - __bfloat162float(h23.x));
    l23.y = __float2bfloat16(v.w - __bfloat162float(h23.y));
    *(__nv_bfloat162*)(hi + i)     = h01;
    *(__nv_bfloat162*)(hi + i + 2) = h23;
    *(__nv_bfloat162*)(lo + i)     = l01;
    *(__nv_bfloat162*)(lo + i + 2) = l23;
}

// ---------------------------------------------------------------------------
// out2[t] = states[t+1] - states[t]
// ---------------------------------------------------------------------------
__global__ void diff_kernel(const float* __restrict__ s0,
                            const float* __restrict__ out0,
                            float* __restrict__ out2)
{
    long long idx = ((long long)blockIdx.x * blockDim.x + threadIdx.x) * 4;
    const long long total = 63LL * ND;
    if (idx >= total) return;
    const int t = (int)(idx / ND);
    const long long r = idx - (long long)t * ND;
    const float* sp1 = out0 + (long long)(t + 1) * ND + r;
    const float* sp0 = (t == 0) ? (s0 + r) : (out0 + (long long)t * ND + r);
    float4 a = *(const float4*)sp1;
    float4 b = *(const float4*)sp0;
    float4 d;
    d.x = a.x - b.x; d.y = a.y - b.y; d.z = a.z - b.z; d.w = a.w - b.w;
    *(float4*)(out2 + idx) = d;
}

// ---------------------------------------------------------------------------
// Inputs: static [64,2048,512], thr [64,2048,1], h0 [2048,512], w1 [1024,512]
// Output: out0 [64,2048,512] | out1 [2048,512] | out2 [63,2048,512]
// ---------------------------------------------------------------------------
extern "C" void kernel_launch(void* const* d_in, const int* in_sizes, int n_in,
                              void* d_out, int out_size)
{
    const float* S   = (const float*)d_in[0];
    const float* thr = (const float*)d_in[1];
    const float* h0  = (const float*)d_in[2];
    const float* W   = (const float*)d_in[3];

    float* out0 = (float*)d_out;
    float* out1 = out0 + (long long)TT * ND;
    float* out2 = out1 + ND;

    float* s0 = nullptr;
    __nv_bfloat16 *hhi = nullptr, *hlo = nullptr, *wth = nullptr, *wtl = nullptr;
    __nv_bfloat16 *shi = nullptr, *slo = nullptr;
    cudaGetSymbolAddress((void**)&s0, g_state0);
    cudaGetSymbolAddress((void**)&hhi, g_h_hi);
    cudaGetSymbolAddress((void**)&hlo, g_h_lo);
    cudaGetSymbolAddress((void**)&wth, g_wt_hi);
    cudaGetSymbolAddress((void**)&wtl, g_wt_lo);
    cudaGetSymbolAddress((void**)&shi, g_s_hi);
    cudaGetSymbolAddress((void**)&slo, g_s_lo);
    __nv_bfloat16* hhi_b[2] = {hhi, hhi + ND};
    __nv_bfloat16* hlo_b[2] = {hlo, hlo + ND};

    cudaFuncSetAttribute(step_mma_kernel,
                         cudaFuncAttributeMaxDynamicSharedMemorySize, SMEM_TOTAL);

    // one-time prep (per launch)
    prep_w_kernel<<<dim3(16, 32), dim3(32, 8)>>>(W, wth, wtl);
    split_kernel<<<ND / 4 / 256, 256>>>(h0, hhi_b[0], hlo_b[0], (long long)ND);
    split_kernel<<<(unsigned)((long long)TT * ND / 4 / 256), 256>>>(
        S, shi, slo, (long long)TT * ND);

    const dim3 grid(DD / BN, NROWS / BM);  // (8, 16) = 128 CTAs

    // t = 0: carry-only state -> scratch; reads split buf0, writes buf1
    step_mma_kernel<<<grid, 256, SMEM_TOTAL>>>(
        hhi_b[0], hlo_b[0], shi, slo, h0, thr, wth, wtl,
        s0, hhi_b[1], hlo_b[1]);
    cudaMemcpyAsync(out0, h0, (size_t)ND * sizeof(float), cudaMemcpyDeviceToDevice);

    for (int t = 1; t < TT; ++t) {
        const int in = t & 1;
        const float* hp = (t == 1) ? (const float*)s0
                                   : (out0 + (long long)(t - 1) * ND);
        step_mma_kernel<<<grid, 256, SMEM_TOTAL>>>(
            hhi_b[in], hlo_b[in],
            shi + (long long)t * ND, slo + (long long)t * ND,
            hp, thr + (long long)t * NROWS,
            wth, wtl,
            out0 + (long long)t * ND,
            hhi_b[in ^ 1], hlo_b[in ^ 1]);
    }

    cudaMemcpyAsync(out1, out0 + 63LL * ND, (size_t)ND * sizeof(float),
                    cudaMemcpyDeviceToDevice);

    const long long total4 = (63LL * ND) / 4;
    const int threads = 256;
    const unsigned blocks = (unsigned)((total4 + threads - 1) / threads);
    diff_kernel<<<blocks, threads>>>(s0, out0, out2);
}